// round 8
// baseline (speedup 1.0000x reference)
#include <cuda_runtime.h>
#include <math.h>

// Problem dims
#define BSZ 4096
#define TT  48
#define DD  32
#define HH  256
#define LL  128
#define EE  8
#define NHH 48

// Output layout: hazard[B,48] | survival[B,48] | z0_mean[B,128] | z0_logvar[B,128] | p_global[B]
#define OH      0
#define OSURV   (BSZ*NHH)
#define OMEAN   (2*BSZ*NHH)
#define OLOGVAR (2*BSZ*NHH + BSZ*LL)
#define OPG     (2*BSZ*NHH + 2*BSZ*LL)

typedef unsigned long long ull;

// Device-global scratch (no allocation allowed)
__device__ float g_z[BSZ*LL];          // z0 handed from GRU to ODE kernel
__device__ float g_wTih[64*768];       // w_ih^T  (k-major)
__device__ float g_wThh[256*768];      // w_hh^T
__device__ float g_z0wT[256*256];      // z0_w^T
__device__ float g_w1T[136*256];       // ode_w1^T
__device__ float g_w2T[256*256];       // ode_w2^T
__device__ float g_w3T[256*128];       // ode_w3^T

// ---------------------------------------------------------------------------
// Packed fp32 helpers (sm_103a f32x2)
// ---------------------------------------------------------------------------
__device__ __forceinline__ void fma2(ull& d, ull a, ull b) {
    asm("fma.rn.f32x2 %0, %1, %2, %0;" : "+l"(d) : "l"(a), "l"(b));
}
__device__ __forceinline__ ull dup2(float v) {
    ull d; asm("mov.b64 %0, {%1, %1};" : "=l"(d) : "f"(v)); return d;
}
__device__ __forceinline__ float2 unpk(ull d) {
    float2 f; asm("mov.b64 {%0, %1}, %2;" : "=f"(f.x), "=f"(f.y) : "l"(d)); return f;
}
__device__ __forceinline__ float sigf(float x) { return 1.f / (1.f + expf(-x)); }

// ---------------------------------------------------------------------------
// Weight transpose prep: dst[k*J + j] = src[j*K + k].  which selects dst.
// ---------------------------------------------------------------------------
__global__ void transpose_kernel(const float* __restrict__ src, int J, int K, int which) {
    int idx = blockIdx.x * 256 + threadIdx.x;
    if (idx >= J * K) return;
    int j = idx / K, k = idx - j * K;
    float* dst;
    switch (which) {
        case 0: dst = g_wTih; break;
        case 1: dst = g_wThh; break;
        case 2: dst = g_z0wT; break;
        case 3: dst = g_w1T;  break;
        case 4: dst = g_w2T;  break;
        default: dst = g_w3T; break;
    }
    dst[(size_t)k * J + j] = src[idx];
}

// ---------------------------------------------------------------------------
// GRU encoder + z0 head.  Grid 128 x 256 threads; 32 batch rows per block.
// Activations live in SMEM as duplicated (v,v) 64-bit pairs for f32x2 FMAs.
// Weights read from global k-major arrays (j-contiguous -> packed pairs free).
// ---------------------------------------------------------------------------
#define GRU_SMEM (32*320*8 + 32*256*4 + 32*256*4 + 512*4 + 32*4)

__global__ __launch_bounds__(256) void gru_kernel(
    const float* __restrict__ X, const float* __restrict__ Mk,
    const float* __restrict__ b_ih, const float* __restrict__ b_hh,
    const float* __restrict__ z0b, float* __restrict__ out)
{
    extern __shared__ ull sm_u[];
    ull*   adup = sm_u;                                   // [32][320] dup pairs: x(32)|mask(32)|h(256)
    float* rs   = (float*)(adup + 32*320);                // [32][256] r gate
    float* zsg  = rs + 32*256;                            // [32][256] z gate
    float* bsum = zsg + 32*256;                           // [512] b_ih+b_hh for r,z
    float* obs  = bsum + 512;                             // [32]

    const int tid  = threadIdx.x;
    const int rb   = blockIdx.x * 32;
    const int rowg = tid >> 6;       // 0..3  -> rows rowg*8 .. +7
    const int colg = tid & 63;       // 0..63

    for (int i = tid; i < 32*256; i += 256) adup[(i >> 8)*320 + 64 + (i & 255)] = 0ULL;
    for (int i = tid; i < 512; i += 256) bsum[i] = b_ih[i] + b_hh[i];
    __syncthreads();

    for (int t = TT - 1; t >= 0; --t) {
        // load X_t / mask_t as dup pairs
        for (int i = tid; i < 32*32; i += 256) {
            int r = i >> 5, d = i & 31;
            size_t off = ((size_t)(rb + r) * TT + t) * DD + d;
            adup[r*320 + d]      = dup2(X[off]);
            adup[r*320 + 32 + d] = dup2(Mk[off]);
        }
        __syncthreads();
        if (tid < 32) {
            float s = 0.f;
            #pragma unroll
            for (int d = 0; d < 32; ++d)
                s += *reinterpret_cast<const float*>(adup + tid*320 + 32 + d);
            obs[tid] = (s > 0.f) ? 1.f : 0.f;
        }
        __syncthreads();

        // ---- r,z pass: 512 gate cols; thread tile 8 rows x 8 cols ----
        {
            const int jb = colg * 8;                     // 0..504
            ull acc[8][4];
            const ull* bs = (const ull*)bsum;
            #pragma unroll
            for (int r = 0; r < 8; ++r)
                #pragma unroll
                for (int c = 0; c < 4; ++c) acc[r][c] = bs[(jb >> 1) + c];

            #pragma unroll 2
            for (int k = 0; k < 64; ++k) {
                const float* wr = g_wTih + (size_t)k*768 + jb;
                ulonglong2 w0 = *(const ulonglong2*)wr;
                ulonglong2 w1 = *(const ulonglong2*)(wr + 4);
                #pragma unroll
                for (int r = 0; r < 8; ++r) {
                    ull av = adup[(rowg*8 + r)*320 + k];
                    fma2(acc[r][0], av, w0.x); fma2(acc[r][1], av, w0.y);
                    fma2(acc[r][2], av, w1.x); fma2(acc[r][3], av, w1.y);
                }
            }
            #pragma unroll 2
            for (int k = 0; k < 256; ++k) {
                const float* wr = g_wThh + (size_t)k*768 + jb;
                ulonglong2 w0 = *(const ulonglong2*)wr;
                ulonglong2 w1 = *(const ulonglong2*)(wr + 4);
                #pragma unroll
                for (int r = 0; r < 8; ++r) {
                    ull av = adup[(rowg*8 + r)*320 + 64 + k];
                    fma2(acc[r][0], av, w0.x); fma2(acc[r][1], av, w0.y);
                    fma2(acc[r][2], av, w1.x); fma2(acc[r][3], av, w1.y);
                }
            }
            #pragma unroll
            for (int r = 0; r < 8; ++r) {
                int row = rowg*8 + r;
                #pragma unroll
                for (int c = 0; c < 4; ++c) {
                    float2 f = unpk(acc[r][c]);
                    int j0 = jb + 2*c;
                    float s0 = sigf(f.x), s1 = sigf(f.y);
                    if (j0 < 256) { rs[row*256 + j0] = s0; rs[row*256 + j0 + 1] = s1; }
                    else          { zsg[row*256 + j0 - 256] = s0; zsg[row*256 + j0 - 255] = s1; }
                }
            }
        }
        __syncthreads();

        // ---- n pass: 256 cols; thread tile 8 rows x 4 cols; separate gi/gh ----
        {
            const int jb4 = colg * 4;                    // 0..252 -> gate col 512+u
            ull acci[8][2], acch[8][2];
            {
                ulonglong2 bi = *(const ulonglong2*)(b_ih + 512 + jb4);
                ulonglong2 bh = *(const ulonglong2*)(b_hh + 512 + jb4);
                #pragma unroll
                for (int r = 0; r < 8; ++r) {
                    acci[r][0] = bi.x; acci[r][1] = bi.y;
                    acch[r][0] = bh.x; acch[r][1] = bh.y;
                }
            }
            #pragma unroll 2
            for (int k = 0; k < 64; ++k) {
                ulonglong2 w = *(const ulonglong2*)(g_wTih + (size_t)k*768 + 512 + jb4);
                #pragma unroll
                for (int r = 0; r < 8; ++r) {
                    ull av = adup[(rowg*8 + r)*320 + k];
                    fma2(acci[r][0], av, w.x); fma2(acci[r][1], av, w.y);
                }
            }
            #pragma unroll 2
            for (int k = 0; k < 256; ++k) {
                ulonglong2 w = *(const ulonglong2*)(g_wThh + (size_t)k*768 + 512 + jb4);
                #pragma unroll
                for (int r = 0; r < 8; ++r) {
                    ull av = adup[(rowg*8 + r)*320 + 64 + k];
                    fma2(acch[r][0], av, w.x); fma2(acch[r][1], av, w.y);
                }
            }
            // epilogue: reads of old h / r / z, then barrier, then writes
            float hv[8][4];
            #pragma unroll
            for (int r = 0; r < 8; ++r) {
                int row = rowg*8 + r;
                float2 i0 = unpk(acci[r][0]), i1 = unpk(acci[r][1]);
                float2 h0 = unpk(acch[r][0]), h1 = unpk(acch[r][1]);
                float iv[4] = {i0.x, i0.y, i1.x, i1.y};
                float hg[4] = {h0.x, h0.y, h1.x, h1.y};
                float o = obs[row];
                #pragma unroll
                for (int c = 0; c < 4; ++c) {
                    int u = jb4 + c;
                    float rr = rs[row*256 + u];
                    float zz = zsg[row*256 + u];
                    float hold = *reinterpret_cast<const float*>(adup + row*320 + 64 + u);
                    float nn   = tanhf(iv[c] + rr * hg[c]);
                    float hnew = (1.f - zz) * nn + zz * hold;
                    hv[r][c]   = o * hnew + (1.f - o) * hold;
                }
            }
            __syncthreads();
            #pragma unroll
            for (int r = 0; r < 8; ++r)
                #pragma unroll
                for (int c = 0; c < 4; ++c)
                    adup[(rowg*8 + r)*320 + 64 + jb4 + c] = dup2(hv[r][c]);
            __syncthreads();
        }
    }

    // ---- z0 head: [32 x 256] = h @ z0_w^T + z0_b ----
    {
        const int jb4 = colg * 4;
        ull acc[8][2];
        ulonglong2 bz = *(const ulonglong2*)(z0b + jb4);
        #pragma unroll
        for (int r = 0; r < 8; ++r) { acc[r][0] = bz.x; acc[r][1] = bz.y; }
        #pragma unroll 2
        for (int k = 0; k < 256; ++k) {
            ulonglong2 w = *(const ulonglong2*)(g_z0wT + (size_t)k*256 + jb4);
            #pragma unroll
            for (int r = 0; r < 8; ++r) {
                ull av = adup[(rowg*8 + r)*320 + 64 + k];
                fma2(acc[r][0], av, w.x); fma2(acc[r][1], av, w.y);
            }
        }
        #pragma unroll
        for (int r = 0; r < 8; ++r) {
            size_t b = rb + rowg*8 + r;
            #pragma unroll
            for (int c = 0; c < 2; ++c) {
                float2 f = unpk(acc[r][c]);
                int j0 = jb4 + 2*c;
                float vv[2] = {f.x, f.y};
                #pragma unroll
                for (int q = 0; q < 2; ++q) {
                    int j = j0 + q; float v = vv[q];
                    if (j < 128) { out[OMEAN + b*128 + j] = v; g_z[b*128 + j] = v; }
                    else         { out[OLOGVAR + b*128 + (j - 128)] = v; }
                }
            }
        }
    }
}

// ---------------------------------------------------------------------------
// Persistent Latent-ODE kernel: 47 RK4 steps + DeepHit hazard + survival.
// Grid 128 x 256 threads; 32 batch rows per block; all state in SMEM.
// ---------------------------------------------------------------------------
#define ODE_SMEM (32*128*8 + 32*256*8 + 32*256*8 + 32*128*4 + 32*128*4 + 256*4 + 32*128*4 + 32*4 + 32*4 + 32*4)

struct OdeSmem {
    ull*   ydup;  ull* h1dup; ull* h2dup;
    float* zs;    float* accs; float* c1;
    float* sw1s;  float* sb1s; float* sw2s; float* cum;
};

__device__ __forceinline__ void hazard_head(
    int j, int rb, int tid, const OdeSmem& S, float sb2v, float* __restrict__ out)
{
    const int row = tid >> 3, sub = tid & 7;
    const float* zr = S.zs + row * 128;
    float hv = 0.f;
    #pragma unroll
    for (int ii = 0; ii < 4; ++ii) {
        int iu = sub*4 + ii;
        const float* wr = S.sw1s + iu*128;
        float s = S.sb1s[iu];
        #pragma unroll 8
        for (int l = 0; l < 128; l += 4) {
            float4 w4 = *(const float4*)(wr + l);
            float4 z4 = *(const float4*)(zr + l);
            s = fmaf(w4.x, z4.x, fmaf(w4.y, z4.y, fmaf(w4.z, z4.z, fmaf(w4.w, z4.w, s))));
        }
        hv += fmaxf(s, 0.f) * S.sw2s[iu];
    }
    hv += __shfl_down_sync(0xffffffffu, hv, 4, 8);
    hv += __shfl_down_sync(0xffffffffu, hv, 2, 8);
    hv += __shfl_down_sync(0xffffffffu, hv, 1, 8);
    if (sub == 0) {
        float hz = sigf(hv + sb2v);
        float c  = S.cum[row];
        size_t b = rb + row;
        out[OH + b*NHH + j] = hz;
        float sv = expf(c);
        out[OSURV + b*NHH + j] = sv;
        if (j == NHH - 1) out[OPG + b] = 1.f - sv;
        S.cum[row] = c + logf(1.f - hz + 1e-7f);
    }
}

// One ODE dynamics eval f(y,t) + RK4 stage epilogue.
// mode 0: accs = zs + ca*k ; y = zs + cy*k
// mode 1: accs += ca*k     ; y = zs + cy*k
// mode 2: zs   = accs+ca*k ; y = zs
__device__ __forceinline__ void ode_stage(
    float t, int mode, float ca, float cy, int tid, const OdeSmem& S,
    const float* __restrict__ b1, const float* __restrict__ b2, const float* __restrict__ b3,
    const float* __restrict__ tpw, const float* __restrict__ tpb)
{
    const int rowg = tid >> 6, colg = tid & 63;

    // c1[j] = b1[j] + sum_e w1T[128+e][j] * temb[e]  (temb recomputed per thread)
    {
        float emb[8];
        #pragma unroll
        for (int m = 0; m < 4; ++m) {
            float ps = t * (float)(m + 1) * 3.14159265358979323846f;
            emb[m] = sinf(ps); emb[4 + m] = cosf(ps);
        }
        float c1v = b1[tid];
        #pragma unroll
        for (int e = 0; e < 8; ++e) {
            float te = tpb[e];
            #pragma unroll
            for (int m = 0; m < 8; ++m) te = fmaf(tpw[e*8 + m], emb[m], te);
            c1v = fmaf(g_w1T[(size_t)(128 + e)*256 + tid], te, c1v);
        }
        S.c1[tid] = c1v;
    }
    __syncthreads();

    // L1: [32 x 256] <- y[32 x 128] @ w1T ; tanh -> h1dup
    {
        const int jb = colg * 4;
        ull acc[8][2];
        ulonglong2 cb = *(const ulonglong2*)(S.c1 + jb);
        #pragma unroll
        for (int r = 0; r < 8; ++r) { acc[r][0] = cb.x; acc[r][1] = cb.y; }
        #pragma unroll 2
        for (int k = 0; k < 128; ++k) {
            ulonglong2 w = *(const ulonglong2*)(g_w1T + (size_t)k*256 + jb);
            #pragma unroll
            for (int r = 0; r < 8; ++r) {
                ull av = S.ydup[(rowg*8 + r)*128 + k];
                fma2(acc[r][0], av, w.x); fma2(acc[r][1], av, w.y);
            }
        }
        #pragma unroll
        for (int r = 0; r < 8; ++r) {
            int row = rowg*8 + r;
            #pragma unroll
            for (int c = 0; c < 2; ++c) {
                float2 f = unpk(acc[r][c]);
                S.h1dup[row*256 + jb + 2*c]     = dup2(tanhf(f.x));
                S.h1dup[row*256 + jb + 2*c + 1] = dup2(tanhf(f.y));
            }
        }
    }
    __syncthreads();

    // L2: [32 x 256] <- h1 @ w2T ; tanh -> h2dup
    {
        const int jb = colg * 4;
        ull acc[8][2];
        ulonglong2 bb = *(const ulonglong2*)(b2 + jb);
        #pragma unroll
        for (int r = 0; r < 8; ++r) { acc[r][0] = bb.x; acc[r][1] = bb.y; }
        #pragma unroll 2
        for (int k = 0; k < 256; ++k) {
            ulonglong2 w = *(const ulonglong2*)(g_w2T + (size_t)k*256 + jb);
            #pragma unroll
            for (int r = 0; r < 8; ++r) {
                ull av = S.h1dup[(rowg*8 + r)*256 + k];
                fma2(acc[r][0], av, w.x); fma2(acc[r][1], av, w.y);
            }
        }
        #pragma unroll
        for (int r = 0; r < 8; ++r) {
            int row = rowg*8 + r;
            #pragma unroll
            for (int c = 0; c < 2; ++c) {
                float2 f = unpk(acc[r][c]);
                S.h2dup[row*256 + jb + 2*c]     = dup2(tanhf(f.x));
                S.h2dup[row*256 + jb + 2*c + 1] = dup2(tanhf(f.y));
            }
        }
    }
    __syncthreads();

    // L3: k = h2 @ w3T  [32 x 128] + RK4 epilogue
    {
        const int jb2 = colg * 2;
        ull acc[8];
        ull bb = *(const ull*)(b3 + jb2);
        #pragma unroll
        for (int r = 0; r < 8; ++r) acc[r] = bb;
        #pragma unroll 2
        for (int k = 0; k < 256; ++k) {
            ull w = *(const ull*)(g_w3T + (size_t)k*128 + jb2);
            #pragma unroll
            for (int r = 0; r < 8; ++r) {
                ull av = S.h2dup[(rowg*8 + r)*256 + k];
                fma2(acc[r], av, w);
            }
        }
        #pragma unroll
        for (int r = 0; r < 8; ++r) {
            int row = rowg*8 + r;
            float2 f = unpk(acc[r]);
            float kk[2] = {f.x, f.y};
            #pragma unroll
            for (int q = 0; q < 2; ++q) {
                int gi = row*128 + jb2 + q;
                float kq = kk[q];
                float yv;
                if (mode == 0)      { S.accs[gi] = S.zs[gi] + ca * kq; yv = S.zs[gi] + cy * kq; }
                else if (mode == 1) { S.accs[gi] += ca * kq;           yv = S.zs[gi] + cy * kq; }
                else                { float zn = S.accs[gi] + ca * kq; S.zs[gi] = zn; yv = zn; }
                S.ydup[gi] = dup2(yv);
            }
        }
    }
    __syncthreads();
}

__global__ __launch_bounds__(256) void ode_kernel(
    float* __restrict__ out,
    const float* __restrict__ b1, const float* __restrict__ b2, const float* __restrict__ b3,
    const float* __restrict__ tpw, const float* __restrict__ tpb,
    const float* __restrict__ sw1, const float* __restrict__ sb1,
    const float* __restrict__ sw2, const float* __restrict__ sb2)
{
    extern __shared__ ull sm_u[];
    OdeSmem S;
    S.ydup  = sm_u;                         // 32*128 ull
    S.h1dup = S.ydup + 32*128;              // 32*256 ull
    S.h2dup = S.h1dup + 32*256;             // 32*256 ull
    S.zs    = (float*)(S.h2dup + 32*256);   // 32*128
    S.accs  = S.zs + 32*128;                // 32*128
    S.c1    = S.accs + 32*128;              // 256
    S.sw1s  = S.c1 + 256;                   // 32*128
    S.sb1s  = S.sw1s + 32*128;              // 32
    S.sw2s  = S.sb1s + 32;                  // 32
    S.cum   = S.sw2s + 32;                  // 32

    const int tid = threadIdx.x;
    const int rb  = blockIdx.x * 32;
    const float sb2v = sb2[0];

    for (int i = tid; i < 32*128; i += 256) S.sw1s[i] = sw1[i];
    if (tid < 32) { S.sb1s[tid] = sb1[tid]; S.sw2s[tid] = sw2[tid]; S.cum[tid] = 0.f; }
    for (int i = tid; i < 32*128; i += 256) {
        float v = g_z[(size_t)rb*128 + i];
        S.zs[i] = v; S.ydup[i] = dup2(v);
    }
    __syncthreads();

    hazard_head(0, rb, tid, S, sb2v, out);
    __syncthreads();

    const double hd = 1.0 / 47.0;
    const float h6  = (float)(hd / 6.0), h3 = (float)(hd / 3.0);
    const float h2f = (float)(hd / 2.0), hf = (float)hd;

    for (int i = 0; i < 47; ++i) {
        float t0 = (float)((double)i / 47.0);
        float tm = (float)(((double)i + 0.5) / 47.0);
        float t1 = (float)((double)(i + 1) / 47.0);
        ode_stage(t0, 0, h6, h2f, tid, S, b1, b2, b3, tpw, tpb);  // k1
        ode_stage(tm, 1, h3, h2f, tid, S, b1, b2, b3, tpw, tpb);  // k2
        ode_stage(tm, 1, h3, hf,  tid, S, b1, b2, b3, tpw, tpb);  // k3
        ode_stage(t1, 2, h6, 0.f, tid, S, b1, b2, b3, tpw, tpb);  // k4 -> z
        hazard_head(i + 1, rb, tid, S, sb2v, out);
        __syncthreads();
    }
}

// ---------------------------------------------------------------------------
extern "C" void kernel_launch(void* const* d_in, const int* in_sizes, int n_in,
                              void* d_out, int out_size)
{
    const float* X     = (const float*)d_in[0];
    const float* Mk    = (const float*)d_in[1];
    const float* gw_ih = (const float*)d_in[2];
    const float* gw_hh = (const float*)d_in[3];
    const float* gb_ih = (const float*)d_in[4];
    const float* gb_hh = (const float*)d_in[5];
    const float* z0w   = (const float*)d_in[6];
    const float* z0b   = (const float*)d_in[7];
    const float* tpw   = (const float*)d_in[8];
    const float* tpb   = (const float*)d_in[9];
    const float* w1    = (const float*)d_in[10];
    const float* b1    = (const float*)d_in[11];
    const float* w2    = (const float*)d_in[12];
    const float* b2    = (const float*)d_in[13];
    const float* w3    = (const float*)d_in[14];
    const float* b3    = (const float*)d_in[15];
    const float* sw1   = (const float*)d_in[16];
    const float* sb1   = (const float*)d_in[17];
    const float* sw2   = (const float*)d_in[18];
    const float* sb2   = (const float*)d_in[19];
    float* out = (float*)d_out;

    cudaFuncSetAttribute(gru_kernel, cudaFuncAttributeMaxDynamicSharedMemorySize, GRU_SMEM);
    cudaFuncSetAttribute(ode_kernel, cudaFuncAttributeMaxDynamicSharedMemorySize, ODE_SMEM);

    // Weight transposes to k-major device-global scratch
    transpose_kernel<<<(768*64  + 255)/256, 256>>>(gw_ih, 768, 64,  0);
    transpose_kernel<<<(768*256 + 255)/256, 256>>>(gw_hh, 768, 256, 1);
    transpose_kernel<<<(256*256 + 255)/256, 256>>>(z0w,   256, 256, 2);
    transpose_kernel<<<(256*136 + 255)/256, 256>>>(w1,    256, 136, 3);
    transpose_kernel<<<(256*256 + 255)/256, 256>>>(w2,    256, 256, 4);
    transpose_kernel<<<(128*256 + 255)/256, 256>>>(w3,    128, 256, 5);

    // GRU encoder + z0 head
    gru_kernel<<<BSZ/32, 256, GRU_SMEM>>>(X, Mk, gb_ih, gb_hh, z0b, out);

    // Persistent RK4 latent ODE + DeepHit hazard + survival
    ode_kernel<<<BSZ/32, 256, ODE_SMEM>>>(out, b1, b2, b3, tpw, tpb, sw1, sb1, sw2, sb2);

    (void)in_sizes; (void)n_in; (void)out_size;
}

// round 14
// speedup vs baseline: 1.5067x; 1.5067x over previous
#include <cuda_runtime.h>
#include <math.h>
#include <stdint.h>

// Problem dims
#define BSZ 4096
#define TT  48
#define DD  32
#define LL  128
#define NHH 48

// Output layout: hazard[B,48] | survival[B,48] | z0_mean[B,128] | z0_logvar[B,128] | p_global[B]
#define OH      0
#define OSURV   (BSZ*NHH)
#define OMEAN   (2*BSZ*NHH)
#define OLOGVAR (2*BSZ*NHH + BSZ*LL)
#define OPG     (2*BSZ*NHH + 2*BSZ*LL)

typedef unsigned long long ull;

// Device-global scratch (no allocation allowed); 16B-aligned for cp.async
__device__ __align__(16) float g_z[BSZ*LL];
__device__ __align__(16) float g_wTih[64*768];       // w_ih^T  (k-major)
__device__ __align__(16) float g_wThh[256*768];      // w_hh^T
__device__ __align__(16) float g_z0wT[256*256];      // z0_w^T
__device__ __align__(16) float g_w1T[136*256];       // ode_w1^T
__device__ __align__(16) float g_w2T[256*256];       // ode_w2^T
__device__ __align__(16) float g_w3T[256*128];       // ode_w3^T

// ---------------------------------------------------------------------------
// Packed fp32 + cp.async helpers
// ---------------------------------------------------------------------------
__device__ __forceinline__ void fma2(ull& d, ull a, ull b) {
    asm("fma.rn.f32x2 %0, %1, %2, %0;" : "+l"(d) : "l"(a), "l"(b));
}
__device__ __forceinline__ ull dup2(float v) {
    ull d; asm("mov.b64 %0, {%1, %1};" : "=l"(d) : "f"(v)); return d;
}
__device__ __forceinline__ float2 unpk(ull d) {
    float2 f; asm("mov.b64 {%0, %1}, %2;" : "=f"(f.x), "=f"(f.y) : "l"(d)); return f;
}
__device__ __forceinline__ float sigf(float x) { return 1.f / (1.f + expf(-x)); }

__device__ __forceinline__ uint32_t s2u(const void* p) {
    return (uint32_t)__cvta_generic_to_shared(p);
}
__device__ __forceinline__ void cpa16(uint32_t dst, const float* src) {
    asm volatile("cp.async.ca.shared.global [%0], [%1], 16;" :: "r"(dst), "l"(src));
}
#define CP_COMMIT() asm volatile("cp.async.commit_group;" ::: "memory")
#define CP_WAIT1()  asm volatile("cp.async.wait_group 1;" ::: "memory")
#define CP_WAIT0()  asm volatile("cp.async.wait_group 0;" ::: "memory")

// All weight tiles are exactly 4096 floats (16KB): 4 cp.async per thread.
__device__ __forceinline__ void stage_lin(uint32_t dst, const float* src, int tid) {
    #pragma unroll
    for (int i = 0; i < 4; ++i)
        cpa16(dst + (uint32_t)(tid + i*256)*16u, src + (size_t)(tid + i*256)*4);
}
template<int COLS4>  // float4 chunks per source row
__device__ __forceinline__ void stage_str(uint32_t dst, const float* src, int strideF, int tid) {
    #pragma unroll
    for (int i = 0; i < 4; ++i) {
        int idx = tid + i*256;
        int r = idx / COLS4, c = idx - r*COLS4;
        cpa16(dst + (uint32_t)idx*16u, src + (size_t)r*strideF + (size_t)c*4);
    }
}

// ---------------------------------------------------------------------------
// Weight transpose prep: dst[k*J + j] = src[j*K + k].
// ---------------------------------------------------------------------------
__global__ void transpose_kernel(const float* __restrict__ src, int J, int K, int which) {
    int idx = blockIdx.x * 256 + threadIdx.x;
    if (idx >= J * K) return;
    int j = idx / K, k = idx - j * K;
    float* dst;
    switch (which) {
        case 0: dst = g_wTih; break;
        case 1: dst = g_wThh; break;
        case 2: dst = g_z0wT; break;
        case 3: dst = g_w1T;  break;
        case 4: dst = g_w2T;  break;
        default: dst = g_w3T; break;
    }
    dst[(size_t)k * J + j] = src[idx];
}

// ---------------------------------------------------------------------------
// GRU encoder + z0 head.  128 blocks x 256 threads; 32 batch rows per block.
// Weight k-tiles staged SMEM via cp.async double buffer (kills 4x LDG
// redundancy + latency exposure). Activations dup'd (v,v) for f32x2.
// ---------------------------------------------------------------------------
#define GRU_SMEM (32*320*8 + 32*256*4 + 32*256*4 + 2*4096*4 + 512*4 + 128)

__global__ __launch_bounds__(256) void gru_kernel(
    const float* __restrict__ X, const float* __restrict__ Mk,
    const float* __restrict__ b_ih, const float* __restrict__ b_hh,
    const float* __restrict__ z0b, float* __restrict__ out)
{
    extern __shared__ ull sm_u[];
    ull*   adup = sm_u;                        // [32][320]: x(32)|mask(32)|h(256)
    float* rs   = (float*)(adup + 32*320);     // [32][256]
    float* zsg  = rs + 32*256;                 // [32][256]
    float* wbuf = zsg + 32*256;                // 2 x 4096 floats
    float* bsum = wbuf + 2*4096;               // [512]
    float* obs  = bsum + 512;                  // [32]

    const int tid  = threadIdx.x;
    const int rb   = blockIdx.x * 32;
    const int rowg = tid >> 6;        // 0..3
    const int colg = tid & 63;        // 0..63
    const int jb   = colg * 8;        // rz column base
    const int jb4  = colg * 4;        // n / z0 column base
    const uint32_t wb0 = s2u(wbuf), wb1 = s2u(wbuf + 4096);

    for (int i = tid; i < 32*256; i += 256) adup[(i >> 8)*320 + 64 + (i & 255)] = 0ULL;
    for (int i = tid; i < 512; i += 256) bsum[i] = b_ih[i] + b_hh[i];
    __syncthreads();

    for (int t = TT - 1; t >= 0; --t) {
        // prologue: rz tiles 0,1 (overlap with X/mask loads)
        stage_str<128>(wb0, g_wTih,          768, tid); CP_COMMIT();
        stage_str<128>(wb1, g_wTih + 8*768,  768, tid); CP_COMMIT();

        for (int i = tid; i < 32*32; i += 256) {
            int r = i >> 5, d = i & 31;
            size_t off = ((size_t)(rb + r) * TT + t) * DD + d;
            adup[r*320 + d]      = dup2(X[off]);
            adup[r*320 + 32 + d] = dup2(Mk[off]);
        }
        __syncthreads();
        if (tid < 32) {
            float s = 0.f;
            #pragma unroll
            for (int d = 0; d < 32; ++d)
                s += *reinterpret_cast<const float*>(adup + tid*320 + 32 + d);
            obs[tid] = (s > 0.f) ? 1.f : 0.f;
        }

        // ---- r,z pass: 40 tiles of 8 k-rows x 512 cols ----
        ull acc[8][4];
        {
            const ull* bs = (const ull*)bsum;
            #pragma unroll
            for (int r = 0; r < 8; ++r)
                #pragma unroll
                for (int c = 0; c < 4; ++c) acc[r][c] = bs[(jb >> 1) + c];
        }
        for (int ti = 0; ti < 40; ++ti) {
            if (ti < 39) CP_WAIT1(); else CP_WAIT0();
            __syncthreads();
            const float* wt = wbuf + (ti & 1)*4096;
            const int aoff = (ti < 8) ? ti*8 : 64 + (ti - 8)*8;
            #pragma unroll 4
            for (int k = 0; k < 8; ++k) {
                ulonglong2 w0 = *(const ulonglong2*)(wt + k*512 + jb);
                ulonglong2 w1 = *(const ulonglong2*)(wt + k*512 + jb + 4);
                #pragma unroll
                for (int r = 0; r < 8; ++r) {
                    ull av = adup[(rowg*8 + r)*320 + aoff + k];
                    fma2(acc[r][0], av, w0.x); fma2(acc[r][1], av, w0.y);
                    fma2(acc[r][2], av, w1.x); fma2(acc[r][3], av, w1.y);
                }
            }
            __syncthreads();
            if (ti + 2 < 40) {
                int tn = ti + 2;
                const float* src = (tn < 8) ? g_wTih + (size_t)tn*8*768
                                            : g_wThh + (size_t)(tn - 8)*8*768;
                stage_str<128>(s2u(wbuf + (ti & 1)*4096), src, 768, tid); CP_COMMIT();
            }
        }
        // prologue n tiles (overlap with rz epilogue)
        stage_str<64>(wb0, g_wTih + 512,            768, tid); CP_COMMIT();
        stage_str<64>(wb1, g_wTih + 16*768 + 512,   768, tid); CP_COMMIT();
        // rz epilogue
        #pragma unroll
        for (int r = 0; r < 8; ++r) {
            int row = rowg*8 + r;
            #pragma unroll
            for (int c = 0; c < 4; ++c) {
                float2 f = unpk(acc[r][c]);
                int j0 = jb + 2*c;
                float s0 = sigf(f.x), s1 = sigf(f.y);
                if (j0 < 256) { rs[row*256 + j0] = s0; rs[row*256 + j0 + 1] = s1; }
                else          { zsg[row*256 + j0 - 256] = s0; zsg[row*256 + j0 - 255] = s1; }
            }
        }

        // ---- n pass: 20 tiles of 16 k-rows x 256 cols (4 ih + 16 hh) ----
        ull acci[8][2], acch[8][2];
        {
            ulonglong2 bi = *(const ulonglong2*)(b_ih + 512 + jb4);
            ulonglong2 bh = *(const ulonglong2*)(b_hh + 512 + jb4);
            #pragma unroll
            for (int r = 0; r < 8; ++r) {
                acci[r][0] = bi.x; acci[r][1] = bi.y;
                acch[r][0] = bh.x; acch[r][1] = bh.y;
            }
        }
        for (int ti = 0; ti < 20; ++ti) {
            if (ti < 19) CP_WAIT1(); else CP_WAIT0();
            __syncthreads();
            const float* wt = wbuf + (ti & 1)*4096;
            if (ti < 4) {
                const int aoff = ti*16;
                #pragma unroll 4
                for (int k = 0; k < 16; ++k) {
                    ulonglong2 w = *(const ulonglong2*)(wt + k*256 + jb4);
                    #pragma unroll
                    for (int r = 0; r < 8; ++r) {
                        ull av = adup[(rowg*8 + r)*320 + aoff + k];
                        fma2(acci[r][0], av, w.x); fma2(acci[r][1], av, w.y);
                    }
                }
            } else {
                const int aoff = 64 + (ti - 4)*16;
                #pragma unroll 4
                for (int k = 0; k < 16; ++k) {
                    ulonglong2 w = *(const ulonglong2*)(wt + k*256 + jb4);
                    #pragma unroll
                    for (int r = 0; r < 8; ++r) {
                        ull av = adup[(rowg*8 + r)*320 + aoff + k];
                        fma2(acch[r][0], av, w.x); fma2(acch[r][1], av, w.y);
                    }
                }
            }
            __syncthreads();
            if (ti + 2 < 20) {
                int tn = ti + 2;
                const float* src = (tn < 4) ? g_wTih + (size_t)tn*16*768 + 512
                                            : g_wThh + (size_t)(tn - 4)*16*768 + 512;
                stage_str<64>(s2u(wbuf + (ti & 1)*4096), src, 768, tid); CP_COMMIT();
            }
        }
        // n epilogue: read old h/r/z -> barrier -> write new h
        float hv[8][4];
        #pragma unroll
        for (int r = 0; r < 8; ++r) {
            int row = rowg*8 + r;
            float2 i0 = unpk(acci[r][0]), i1 = unpk(acci[r][1]);
            float2 h0 = unpk(acch[r][0]), h1 = unpk(acch[r][1]);
            float iv[4] = {i0.x, i0.y, i1.x, i1.y};
            float hg[4] = {h0.x, h0.y, h1.x, h1.y};
            float o = obs[row];
            #pragma unroll
            for (int c = 0; c < 4; ++c) {
                int u = jb4 + c;
                float rr = rs[row*256 + u];
                float zz = zsg[row*256 + u];
                float hold = *reinterpret_cast<const float*>(adup + row*320 + 64 + u);
                float nn   = tanhf(iv[c] + rr * hg[c]);
                float hnew = (1.f - zz) * nn + zz * hold;
                hv[r][c]   = o * hnew + (1.f - o) * hold;
            }
        }
        __syncthreads();
        #pragma unroll
        for (int r = 0; r < 8; ++r)
            #pragma unroll
            for (int c = 0; c < 4; ++c)
                adup[(rowg*8 + r)*320 + 64 + jb4 + c] = dup2(hv[r][c]);
        __syncthreads();
    }

    // ---- z0 head: 16 tiles of 16 k-rows x 256 cols (contiguous) ----
    stage_lin(wb0, g_z0wT,        tid); CP_COMMIT();
    stage_lin(wb1, g_z0wT + 4096, tid); CP_COMMIT();
    ull acc[8][2];
    {
        ulonglong2 bz = *(const ulonglong2*)(z0b + jb4);
        #pragma unroll
        for (int r = 0; r < 8; ++r) { acc[r][0] = bz.x; acc[r][1] = bz.y; }
    }
    for (int ti = 0; ti < 16; ++ti) {
        if (ti < 15) CP_WAIT1(); else CP_WAIT0();
        __syncthreads();
        const float* wt = wbuf + (ti & 1)*4096;
        #pragma unroll 4
        for (int k = 0; k < 16; ++k) {
            ulonglong2 w = *(const ulonglong2*)(wt + k*256 + jb4);
            #pragma unroll
            for (int r = 0; r < 8; ++r) {
                ull av = adup[(rowg*8 + r)*320 + 64 + ti*16 + k];
                fma2(acc[r][0], av, w.x); fma2(acc[r][1], av, w.y);
            }
        }
        __syncthreads();
        if (ti + 2 < 16) {
            stage_lin(s2u(wbuf + (ti & 1)*4096), g_z0wT + (size_t)(ti + 2)*4096, tid);
            CP_COMMIT();
        }
    }
    #pragma unroll
    for (int r = 0; r < 8; ++r) {
        size_t b = rb + rowg*8 + r;
        #pragma unroll
        for (int c = 0; c < 2; ++c) {
            float2 f = unpk(acc[r][c]);
            int j0 = jb4 + 2*c;
            float vv[2] = {f.x, f.y};
            #pragma unroll
            for (int q = 0; q < 2; ++q) {
                int j = j0 + q; float v = vv[q];
                if (j < 128) { out[OMEAN + b*128 + j] = v; g_z[b*128 + j] = v; }
                else         { out[OLOGVAR + b*128 + (j - 128)] = v; }
            }
        }
    }
}

// ---------------------------------------------------------------------------
// Persistent Latent-ODE kernel: 47 RK4 steps + DeepHit hazard + survival.
// RK4 accumulator lives in registers; weight tiles cp.async double-buffered.
// ---------------------------------------------------------------------------
#define ODE_SMEM (32*128*8 + 32*256*8 + 32*256*8 + 32*128*4 + 256*4 + 2*4096*4 + 128)

__device__ __forceinline__ void hazard_head(
    int j, int rb, int tid, const float* zs, float* cum,
    const float* __restrict__ sw1, const float* __restrict__ sb1,
    const float* __restrict__ sw2, float sb2v, float* __restrict__ out)
{
    const int row = tid >> 3, sub = tid & 7;
    const float* zr = zs + row * 128;
    float hv = 0.f;
    #pragma unroll
    for (int ii = 0; ii < 4; ++ii) {
        int iu = sub*4 + ii;
        const float* wr = sw1 + iu*128;
        float s = sb1[iu];
        #pragma unroll 8
        for (int l = 0; l < 128; l += 4) {
            float4 w4 = *(const float4*)(wr + l);
            float4 z4 = *(const float4*)(zr + l);
            s = fmaf(w4.x, z4.x, fmaf(w4.y, z4.y, fmaf(w4.z, z4.z, fmaf(w4.w, z4.w, s))));
        }
        hv += fmaxf(s, 0.f) * sw2[iu];
    }
    hv += __shfl_down_sync(0xffffffffu, hv, 4, 8);
    hv += __shfl_down_sync(0xffffffffu, hv, 2, 8);
    hv += __shfl_down_sync(0xffffffffu, hv, 1, 8);
    if (sub == 0) {
        float hz = sigf(hv + sb2v);
        float c  = cum[row];
        size_t b = rb + row;
        out[OH + b*NHH + j] = hz;
        float sv = expf(c);
        out[OSURV + b*NHH + j] = sv;
        if (j == NHH - 1) out[OPG + b] = 1.f - sv;
        cum[row] = c + logf(1.f - hz + 1e-7f);
    }
}

// mode 0: accR = zs + ca*k ; y = zs + cy*k
// mode 1: accR += ca*k     ; y = zs + cy*k
// mode 2: zs = accR + ca*k ; y = zs
__device__ __forceinline__ void ode_stage(
    float t, int mode, float ca, float cy, int tid,
    ull* ydup, ull* h1dup, ull* h2dup, float* zs, float* c1, float* wbuf,
    float (&accR)[8][2],
    const float* __restrict__ b1, const float* __restrict__ b2, const float* __restrict__ b3,
    const float* __restrict__ tpw, const float* __restrict__ tpb)
{
    const int rowg = tid >> 6, colg = tid & 63;
    const int jb = colg * 4, jb2 = colg * 2;
    const uint32_t wb0 = s2u(wbuf), wb1 = s2u(wbuf + 4096);

    // L1 prologue (overlap with c1 compute)
    stage_lin(wb0, g_w1T,        tid); CP_COMMIT();
    stage_lin(wb1, g_w1T + 4096, tid); CP_COMMIT();

    {   // c1[j] = b1[j] + sum_e w1T[128+e][j] * temb[e]
        float emb[8];
        #pragma unroll
        for (int m = 0; m < 4; ++m) {
            float ps = t * (float)(m + 1) * 3.14159265358979323846f;
            emb[m] = sinf(ps); emb[4 + m] = cosf(ps);
        }
        float c1v = b1[tid];
        #pragma unroll
        for (int e = 0; e < 8; ++e) {
            float te = tpb[e];
            #pragma unroll
            for (int m = 0; m < 8; ++m) te = fmaf(tpw[e*8 + m], emb[m], te);
            c1v = fmaf(g_w1T[(size_t)(128 + e)*256 + tid], te, c1v);
        }
        c1[tid] = c1v;
    }

    // L1: 8 tiles of 16 k x 256 cols
    ull acc[8][2];
    for (int ti = 0; ti < 8; ++ti) {
        if (ti < 7) CP_WAIT1(); else CP_WAIT0();
        __syncthreads();
        if (ti == 0) {
            ulonglong2 cb = *(const ulonglong2*)(c1 + jb);
            #pragma unroll
            for (int r = 0; r < 8; ++r) { acc[r][0] = cb.x; acc[r][1] = cb.y; }
        }
        const float* wt = wbuf + (ti & 1)*4096;
        #pragma unroll 4
        for (int k = 0; k < 16; ++k) {
            ulonglong2 w = *(const ulonglong2*)(wt + k*256 + jb);
            #pragma unroll
            for (int r = 0; r < 8; ++r) {
                ull av = ydup[(rowg*8 + r)*128 + ti*16 + k];
                fma2(acc[r][0], av, w.x); fma2(acc[r][1], av, w.y);
            }
        }
        __syncthreads();
        if (ti + 2 < 8) {
            stage_lin(s2u(wbuf + (ti & 1)*4096), g_w1T + (size_t)(ti + 2)*4096, tid);
            CP_COMMIT();
        }
    }
    // L2 prologue (overlap with L1 epilogue)
    stage_lin(wb0, g_w2T,        tid); CP_COMMIT();
    stage_lin(wb1, g_w2T + 4096, tid); CP_COMMIT();
    #pragma unroll
    for (int r = 0; r < 8; ++r) {
        int row = rowg*8 + r;
        #pragma unroll
        for (int c = 0; c < 2; ++c) {
            float2 f = unpk(acc[r][c]);
            h1dup[row*256 + jb + 2*c]     = dup2(tanhf(f.x));
            h1dup[row*256 + jb + 2*c + 1] = dup2(tanhf(f.y));
        }
    }

    // L2: 16 tiles of 16 k x 256 cols
    for (int ti = 0; ti < 16; ++ti) {
        if (ti < 15) CP_WAIT1(); else CP_WAIT0();
        __syncthreads();
        if (ti == 0) {
            ulonglong2 bb = *(const ulonglong2*)(b2 + jb);
            #pragma unroll
            for (int r = 0; r < 8; ++r) { acc[r][0] = bb.x; acc[r][1] = bb.y; }
        }
        const float* wt = wbuf + (ti & 1)*4096;
        #pragma unroll 4
        for (int k = 0; k < 16; ++k) {
            ulonglong2 w = *(const ulonglong2*)(wt + k*256 + jb);
            #pragma unroll
            for (int r = 0; r < 8; ++r) {
                ull av = h1dup[(rowg*8 + r)*256 + ti*16 + k];
                fma2(acc[r][0], av, w.x); fma2(acc[r][1], av, w.y);
            }
        }
        __syncthreads();
        if (ti + 2 < 16) {
            stage_lin(s2u(wbuf + (ti & 1)*4096), g_w2T + (size_t)(ti + 2)*4096, tid);
            CP_COMMIT();
        }
    }
    // L3 prologue (overlap with L2 epilogue)
    stage_lin(wb0, g_w3T,        tid); CP_COMMIT();
    stage_lin(wb1, g_w3T + 4096, tid); CP_COMMIT();
    #pragma unroll
    for (int r = 0; r < 8; ++r) {
        int row = rowg*8 + r;
        #pragma unroll
        for (int c = 0; c < 2; ++c) {
            float2 f = unpk(acc[r][c]);
            h2dup[row*256 + jb + 2*c]     = dup2(tanhf(f.x));
            h2dup[row*256 + jb + 2*c + 1] = dup2(tanhf(f.y));
        }
    }

    // L3: 8 tiles of 32 k x 128 cols
    ull acc3[8];
    for (int ti = 0; ti < 8; ++ti) {
        if (ti < 7) CP_WAIT1(); else CP_WAIT0();
        __syncthreads();
        if (ti == 0) {
            ull bb = *(const ull*)(b3 + jb2);
            #pragma unroll
            for (int r = 0; r < 8; ++r) acc3[r] = bb;
        }
        const float* wt = wbuf + (ti & 1)*4096;
        #pragma unroll 4
        for (int k = 0; k < 32; ++k) {
            ull w = *(const ull*)(wt + k*128 + jb2);
            #pragma unroll
            for (int r = 0; r < 8; ++r) {
                ull av = h2dup[(rowg*8 + r)*256 + ti*32 + k];
                fma2(acc3[r], av, w);
            }
        }
        __syncthreads();
        if (ti + 2 < 8) {
            stage_lin(s2u(wbuf + (ti & 1)*4096), g_w3T + (size_t)(ti + 2)*4096, tid);
            CP_COMMIT();
        }
    }
    // RK4 epilogue
    #pragma unroll
    for (int r = 0; r < 8; ++r) {
        int row = rowg*8 + r;
        float2 f = unpk(acc3[r]);
        float kk[2] = {f.x, f.y};
        #pragma unroll
        for (int q = 0; q < 2; ++q) {
            int gi = row*128 + jb2 + q;
            float kq = kk[q];
            float yv;
            if (mode == 0)      { accR[r][q] = zs[gi] + ca * kq; yv = zs[gi] + cy * kq; }
            else if (mode == 1) { accR[r][q] += ca * kq;         yv = zs[gi] + cy * kq; }
            else                { float zn = accR[r][q] + ca * kq; zs[gi] = zn; yv = zn; }
            ydup[gi] = dup2(yv);
        }
    }
    __syncthreads();
}

__global__ __launch_bounds__(256) void ode_kernel(
    float* __restrict__ out,
    const float* __restrict__ b1, const float* __restrict__ b2, const float* __restrict__ b3,
    const float* __restrict__ tpw, const float* __restrict__ tpb,
    const float* __restrict__ sw1, const float* __restrict__ sb1,
    const float* __restrict__ sw2, const float* __restrict__ sb2)
{
    extern __shared__ ull sm_u[];
    ull*   ydup  = sm_u;                        // 32*128 ull
    ull*   h1dup = ydup + 32*128;               // 32*256 ull
    ull*   h2dup = h1dup + 32*256;              // 32*256 ull
    float* zs    = (float*)(h2dup + 32*256);    // 32*128
    float* c1    = zs + 32*128;                 // 256
    float* wbuf  = c1 + 256;                    // 2*4096
    float* cum   = wbuf + 2*4096;               // 32

    const int tid = threadIdx.x;
    const int rb  = blockIdx.x * 32;
    const float sb2v = sb2[0];

    if (tid < 32) cum[tid] = 0.f;
    for (int i = tid; i < 32*128; i += 256) {
        float v = g_z[(size_t)rb*128 + i];
        zs[i] = v; ydup[i] = dup2(v);
    }
    __syncthreads();

    hazard_head(0, rb, tid, zs, cum, sw1, sb1, sw2, sb2v, out);
    __syncthreads();

    const double hd = 1.0 / 47.0;
    const float h6  = (float)(hd / 6.0), h3 = (float)(hd / 3.0);
    const float h2f = (float)(hd / 2.0), hf = (float)hd;

    float accR[8][2];
    for (int i = 0; i < 47; ++i) {
        float t0 = (float)((double)i / 47.0);
        float tm = (float)(((double)i + 0.5) / 47.0);
        float t1 = (float)((double)(i + 1) / 47.0);
        ode_stage(t0, 0, h6, h2f, tid, ydup, h1dup, h2dup, zs, c1, wbuf, accR, b1, b2, b3, tpw, tpb);
        ode_stage(tm, 1, h3, h2f, tid, ydup, h1dup, h2dup, zs, c1, wbuf, accR, b1, b2, b3, tpw, tpb);
        ode_stage(tm, 1, h3, hf,  tid, ydup, h1dup, h2dup, zs, c1, wbuf, accR, b1, b2, b3, tpw, tpb);
        ode_stage(t1, 2, h6, 0.f, tid, ydup, h1dup, h2dup, zs, c1, wbuf, accR, b1, b2, b3, tpw, tpb);
        hazard_head(i + 1, rb, tid, zs, cum, sw1, sb1, sw2, sb2v, out);
        __syncthreads();
    }
}

// ---------------------------------------------------------------------------
extern "C" void kernel_launch(void* const* d_in, const int* in_sizes, int n_in,
                              void* d_out, int out_size)
{
    const float* X     = (const float*)d_in[0];
    const float* Mk    = (const float*)d_in[1];
    const float* gw_ih = (const float*)d_in[2];
    const float* gw_hh = (const float*)d_in[3];
    const float* gb_ih = (const float*)d_in[4];
    const float* gb_hh = (const float*)d_in[5];
    const float* z0w   = (const float*)d_in[6];
    const float* z0b   = (const float*)d_in[7];
    const float* tpw   = (const float*)d_in[8];
    const float* tpb   = (const float*)d_in[9];
    const float* w1    = (const float*)d_in[10];
    const float* b1    = (const float*)d_in[11];
    const float* w2    = (const float*)d_in[12];
    const float* b2    = (const float*)d_in[13];
    const float* w3    = (const float*)d_in[14];
    const float* b3    = (const float*)d_in[15];
    const float* sw1   = (const float*)d_in[16];
    const float* sb1   = (const float*)d_in[17];
    const float* sw2   = (const float*)d_in[18];
    const float* sb2   = (const float*)d_in[19];
    float* out = (float*)d_out;

    cudaFuncSetAttribute(gru_kernel, cudaFuncAttributeMaxDynamicSharedMemorySize, GRU_SMEM);
    cudaFuncSetAttribute(ode_kernel, cudaFuncAttributeMaxDynamicSharedMemorySize, ODE_SMEM);

    transpose_kernel<<<(768*64  + 255)/256, 256>>>(gw_ih, 768, 64,  0);
    transpose_kernel<<<(768*256 + 255)/256, 256>>>(gw_hh, 768, 256, 1);
    transpose_kernel<<<(256*256 + 255)/256, 256>>>(z0w,   256, 256, 2);
    transpose_kernel<<<(256*136 + 255)/256, 256>>>(w1,    256, 136, 3);
    transpose_kernel<<<(256*256 + 255)/256, 256>>>(w2,    256, 256, 4);
    transpose_kernel<<<(128*256 + 255)/256, 256>>>(w3,    128, 256, 5);

    gru_kernel<<<BSZ/32, 256, GRU_SMEM>>>(X, Mk, gb_ih, gb_hh, z0b, out);
    ode_kernel<<<BSZ/32, 256, ODE_SMEM>>>(out, b1, b2, b3, tpw, tpb, sw1, sb1, sw2, sb2);

    (void)in_sizes; (void)n_in; (void)out_size;
}